// round 3
// baseline (speedup 1.0000x reference)
#include <cuda_runtime.h>
#include <math.h>

// Shapes (compile-time constants for this problem instance)
#define HD   768            // H1 == H2
#define NB   8              // batch
#define SLQ  1024           // query length
#define SLK  1024           // key length
#define NH   3              // heads (full-width, stacked)

// ---------------------------------------------------------------------------
// Scratch (device globals: allocation-free, graph-capturable)
// ---------------------------------------------------------------------------
__device__ float g_q[(long)NH * NB * SLQ * HD];          // 75.5 MB  [h][b][m][d]
__device__ float g_k[(long)NH * NB * SLK * HD];          // 75.5 MB
__device__ float g_v[(long)NH * NB * SLK * HD];          // 75.5 MB
__device__ float g_s[(long)NH * NB * SLQ * SLK];         // 100.7 MB [h][b][m][n]
__device__ float g_multi[(long)NB * SLQ * NH * HD];      // 75.5 MB  [b][m][h*768+e]

// ---------------------------------------------------------------------------
// Tiled fp32 GEMM core: C[128x128] per block, BK=16, 8x8 microtile, 256 thr.
// A is row-major [M x K] (lda = K-stride). B is either:
//   NT_B=false: row-major [K x N] (ldb = N-stride)   -> C = A @ B
//   NT_B=true : row-major [N x K] (ldb = K-stride)   -> C = A @ B^T
// RELU_A applies relu to A elements on load.
// All of M, N divisible by 128; K divisible by 16 (true for every call here).
// ---------------------------------------------------------------------------
template <bool NT_B, bool RELU_A>
__device__ __forceinline__ void gemm_tile(
    const float* __restrict__ A, const float* __restrict__ B,
    float* __restrict__ C, const float* __restrict__ bias,
    int K, int lda, int ldb, int ldc)
{
    constexpr int BM = 128, BN = 128, BK = 16;
    __shared__ __align__(16) float sA[BK][BM];   // A^T tile
    __shared__ __align__(16) float sB[BK][BN];   // B tile (k-major)

    const int tid = threadIdx.x;          // 0..255
    const int tx  = tid & 15;             // 0..15
    const int ty  = tid >> 4;             // 0..15
    const int rm  = ty * 8;
    const int rn  = tx * 8;
    const int row0 = blockIdx.y * BM;
    const int col0 = blockIdx.x * BN;

    // A-tile (and NT B-tile) loader mapping: float4 along K
    const int ak = (tid & 3) * 4;         // k-offset within tile
    const int ar = tid >> 2;              // 0..63, two passes (+64)
    // NN B-tile loader mapping: float4 along N
    const int bn = (tid & 31) * 4;        // n-offset
    const int bk = tid >> 5;              // 0..7, two passes (+8)

    float acc[8][8];
#pragma unroll
    for (int i = 0; i < 8; i++)
#pragma unroll
        for (int j = 0; j < 8; j++) acc[i][j] = 0.f;

    for (int k0 = 0; k0 < K; k0 += BK) {
        // ---- load A tile (transpose into sA) ----
#pragma unroll
        for (int p = 0; p < 2; p++) {
            const int r = ar + p * 64;
            float4 v = *(const float4*)(A + (long)(row0 + r) * lda + (k0 + ak));
            if (RELU_A) {
                v.x = fmaxf(v.x, 0.f); v.y = fmaxf(v.y, 0.f);
                v.z = fmaxf(v.z, 0.f); v.w = fmaxf(v.w, 0.f);
            }
            sA[ak + 0][r] = v.x; sA[ak + 1][r] = v.y;
            sA[ak + 2][r] = v.z; sA[ak + 3][r] = v.w;
        }
        // ---- load B tile ----
        if (NT_B) {
#pragma unroll
            for (int p = 0; p < 2; p++) {
                const int r = ar + p * 64;   // n-row of B
                float4 v = *(const float4*)(B + (long)(col0 + r) * ldb + (k0 + ak));
                sB[ak + 0][r] = v.x; sB[ak + 1][r] = v.y;
                sB[ak + 2][r] = v.z; sB[ak + 3][r] = v.w;
            }
        } else {
#pragma unroll
            for (int p = 0; p < 2; p++) {
                const int r = bk + p * 8;    // k-row of B
                *(float4*)&sB[r][bn] =
                    *(const float4*)(B + (long)(k0 + r) * ldb + (col0 + bn));
            }
        }
        __syncthreads();

        // ---- compute ----
#pragma unroll
        for (int kk = 0; kk < BK; kk++) {
            float ra[8], rb[8];
            *(float4*)(ra)     = *(const float4*)&sA[kk][rm];
            *(float4*)(ra + 4) = *(const float4*)&sA[kk][rm + 4];
            *(float4*)(rb)     = *(const float4*)&sB[kk][rn];
            *(float4*)(rb + 4) = *(const float4*)&sB[kk][rn + 4];
#pragma unroll
            for (int i = 0; i < 8; i++)
#pragma unroll
                for (int j = 0; j < 8; j++)
                    acc[i][j] = fmaf(ra[i], rb[j], acc[i][j]);
        }
        __syncthreads();
    }

    // ---- epilogue: optional bias, vectorized store ----
#pragma unroll
    for (int i = 0; i < 8; i++) {
        float* crow = C + (long)(row0 + rm + i) * ldc + (col0 + rn);
#pragma unroll
        for (int j4 = 0; j4 < 8; j4 += 4) {
            float4 v;
            v.x = acc[i][j4 + 0]; v.y = acc[i][j4 + 1];
            v.z = acc[i][j4 + 2]; v.w = acc[i][j4 + 3];
            if (bias) {
                const float* bp = bias + col0 + rn + j4;
                v.x += bp[0]; v.y += bp[1]; v.z += bp[2]; v.w += bp[3];
            }
            *(float4*)(crow + j4) = v;
        }
    }
}

// ---------------------------------------------------------------------------
// Kernel 1: fused QKV projections. blockIdx.z in [0,9): op = z/3, head = z%3
// ---------------------------------------------------------------------------
__global__ __launch_bounds__(256, 2) void qkv_kernel(
    const float* __restrict__ t1, const float* __restrict__ t2,
    const float* __restrict__ Wq, const float* __restrict__ bq,
    const float* __restrict__ Wk, const float* __restrict__ bk,
    const float* __restrict__ Wv, const float* __restrict__ bv)
{
    const int z = blockIdx.z;
    const int op = z / 3;
    const int h  = z - op * 3;
    const long wOff = (long)h * HD * HD;
    const long cOff = (long)h * NB * SLQ * HD;

    const float* A; const float* W; const float* bias; float* Cb;
    if (op == 0)      { A = t1; W = Wq + wOff; bias = bq + h * HD; Cb = g_q + cOff; }
    else if (op == 1) { A = t2; W = Wk + wOff; bias = bk + h * HD; Cb = g_k + cOff; }
    else              { A = t2; W = Wv + wOff; bias = bv + h * HD; Cb = g_v + cOff; }

    gemm_tile<false, false>(A, W, Cb, bias, HD, HD, HD, HD);
}

// ---------------------------------------------------------------------------
// Kernel 2: scores = q @ k^T per (h,b). blockIdx.z = h*8 + b
// ---------------------------------------------------------------------------
__global__ __launch_bounds__(256, 2) void scores_kernel()
{
    const long z = blockIdx.z;
    gemm_tile<true, false>(g_q + z * SLQ * HD, g_k + z * SLK * HD,
                           g_s + z * SLQ * SLK, nullptr,
                           HD, HD, HD, SLK);
}

// ---------------------------------------------------------------------------
// Kernel 3: row softmax over LK, in place. One 256-thread block per row.
// ---------------------------------------------------------------------------
__global__ void softmax_kernel()
{
    float* p = g_s + (long)blockIdx.x * SLK;
    const int tid = threadIdx.x;
    float4 v = reinterpret_cast<float4*>(p)[tid];

    __shared__ float redm[8];
    __shared__ float reds[8];

    // row max
    float m = fmaxf(fmaxf(v.x, v.y), fmaxf(v.z, v.w));
#pragma unroll
    for (int o = 16; o > 0; o >>= 1) m = fmaxf(m, __shfl_xor_sync(0xffffffffu, m, o));
    if ((tid & 31) == 0) redm[tid >> 5] = m;
    __syncthreads();
    if (tid < 32) {
        float t = (tid < 8) ? redm[tid] : -INFINITY;
#pragma unroll
        for (int o = 4; o > 0; o >>= 1) t = fmaxf(t, __shfl_xor_sync(0xffffffffu, t, o));
        if (tid == 0) redm[0] = t;
    }
    __syncthreads();
    m = redm[0];

    // exp + row sum
    v.x = expf(v.x - m); v.y = expf(v.y - m);
    v.z = expf(v.z - m); v.w = expf(v.w - m);
    float s = v.x + v.y + v.z + v.w;
#pragma unroll
    for (int o = 16; o > 0; o >>= 1) s += __shfl_xor_sync(0xffffffffu, s, o);
    if ((tid & 31) == 0) reds[tid >> 5] = s;
    __syncthreads();
    if (tid < 32) {
        float t = (tid < 8) ? reds[tid] : 0.f;
#pragma unroll
        for (int o = 4; o > 0; o >>= 1) t += __shfl_xor_sync(0xffffffffu, t, o);
        if (tid == 0) reds[0] = t;
    }
    __syncthreads();
    const float inv = 1.f / reds[0];

    v.x *= inv; v.y *= inv; v.z *= inv; v.w *= inv;
    reinterpret_cast<float4*>(p)[tid] = v;
}

// ---------------------------------------------------------------------------
// Kernel 4: ctx = P @ v per (h,b), scattered into multi[b][m][h*768 + e]
// ---------------------------------------------------------------------------
__global__ __launch_bounds__(256, 2) void ctx_kernel()
{
    const int z = blockIdx.z;
    const int h = z >> 3;
    const int b = z & 7;
    gemm_tile<false, false>(g_s + (long)z * SLQ * SLK,
                            g_v + (long)z * SLK * HD,
                            g_multi + (long)b * SLQ * (NH * HD) + (long)h * HD,
                            nullptr,
                            SLK, SLK, HD, NH * HD);
}

// ---------------------------------------------------------------------------
// Kernel 5: out = relu(multi) @ Wp + bp
// ---------------------------------------------------------------------------
__global__ __launch_bounds__(256, 2) void proj_kernel(
    const float* __restrict__ Wp, const float* __restrict__ bp,
    float* __restrict__ out)
{
    gemm_tile<false, true>(g_multi, Wp, out, bp, NH * HD, NH * HD, HD, HD);
}

// ---------------------------------------------------------------------------
// Launch
// ---------------------------------------------------------------------------
extern "C" void kernel_launch(void* const* d_in, const int* in_sizes, int n_in,
                              void* d_out, int out_size)
{
    const float* t1 = (const float*)d_in[0];   // [8,1024,768]
    const float* t2 = (const float*)d_in[1];   // [8,1024,768]
    const float* Wq = (const float*)d_in[2];   // [3,768,768]
    const float* bq = (const float*)d_in[3];   // [3,768]
    const float* Wk = (const float*)d_in[4];
    const float* bk = (const float*)d_in[5];
    const float* Wv = (const float*)d_in[6];
    const float* bv = (const float*)d_in[7];
    const float* Wp = (const float*)d_in[8];   // [2304,768]
    const float* bp = (const float*)d_in[9];   // [768]
    float* out = (float*)d_out;                // [8,1024,768]

    // QKV: M=8192, N=768 -> grid (6, 64, 9)
    qkv_kernel<<<dim3(6, 64, 9), 256>>>(t1, t2, Wq, bq, Wk, bk, Wv, bv);
    // scores: M=1024, N=1024 per (h,b) -> grid (8, 8, 24)
    scores_kernel<<<dim3(8, 8, 24), 256>>>();
    // softmax: one block per row, 3*8*1024 rows
    softmax_kernel<<<NH * NB * SLQ, 256>>>();
    // ctx: M=1024, N=768 per (h,b) -> grid (6, 8, 24)
    ctx_kernel<<<dim3(6, 8, 24), 256>>>();
    // proj: M=8192, N=768 -> grid (6, 64, 1)
    proj_kernel<<<dim3(6, 64, 1), 256>>>(Wp, bp, out);
}

// round 7
// speedup vs baseline: 1.0391x; 1.0391x over previous
#include <cuda_runtime.h>
#include <cstdint>
#include <stdint.h>
#include <math.h>

// Shapes (compile-time constants for this problem instance)
#define HD   768            // H1 == H2
#define NB   8              // batch
#define SLQ  1024           // query length
#define SLK  1024           // key length
#define NH   3              // heads (full-width, stacked)

// ---------------------------------------------------------------------------
// Scratch (device globals: allocation-free, graph-capturable)
// ---------------------------------------------------------------------------
__device__ float g_q [(long)NH * NB * SLQ * HD];         // [h][b][m][d]
__device__ float g_k [(long)NH * NB * SLK * HD];         // [h][b][n][d]
__device__ float g_kT[(long)NH * NB * HD * SLK];         // [h][b][d][n]
__device__ float g_v [(long)NH * NB * SLK * HD];         // [h][b][n][d]
__device__ float g_s [(long)NH * NB * SLQ * SLK];        // [h][b][m][n]
__device__ float g_multi[(long)NB * SLQ * NH * HD];      // [b][m][h*768+e]

// ---------------------------------------------------------------------------
// cp.async helpers
// ---------------------------------------------------------------------------
__device__ __forceinline__ void cp16(unsigned saddr, const float* g) {
    asm volatile("cp.async.cg.shared.global [%0], [%1], 16;\n" :: "r"(saddr), "l"(g));
}
__device__ __forceinline__ void cp_commit() {
    asm volatile("cp.async.commit_group;\n" ::: "memory");
}
__device__ __forceinline__ void cp_wait_all() {
    asm volatile("cp.async.wait_group 0;\n" ::: "memory");
}

// ---------------------------------------------------------------------------
// Pipelined fp32 NN GEMM core: C[128x128] per block, BK=16, 8x8 microtile,
// 256 threads, double-buffered smem, cp.async B-tiles, register-staged A.
// A row-major [M x K] (lda), B row-major [K x N] (ldb), C row-major (ldc).
// M, N divisible by 128; K divisible by 16 (true for every call here).
// ---------------------------------------------------------------------------
template <bool RELU_A>
__device__ __forceinline__ void gemm_nn(
    const float* __restrict__ A, const float* __restrict__ B,
    float* __restrict__ C, const float* __restrict__ bias,
    int K, int lda, int ldb, int ldc)
{
    constexpr int BM = 128, BN = 128, BK = 16;
    constexpr int AP = BM + 4;                 // pad: 2-way STS conflict, 16B aligned
    __shared__ __align__(16) float sA[2][BK][AP];
    __shared__ __align__(16) float sB[2][BK][BN];

    const int tid = threadIdx.x;          // 0..255
    const int tx  = tid & 15;
    const int ty  = tid >> 4;
    const int rm  = ty * 8;
    const int rn  = tx * 8;
    const int row0 = blockIdx.y * BM;
    const int col0 = blockIdx.x * BN;

    // A loader: float4 along K, transposed into sA
    const int ak = (tid & 3) * 4;         // k-offset
    const int ar = tid >> 2;              // 0..63 (+64)
    // B loader: 16B chunk along N
    const int bn = (tid & 31) * 4;        // n-offset
    const int bk = tid >> 5;              // 0..7 (+8)

    const unsigned sB_u32 = (unsigned)__cvta_generic_to_shared(&sB[0][0][0]);

    // ---- prologue: tile 0 into buffer 0 ----
#pragma unroll
    for (int p = 0; p < 2; p++) {
        const int r = bk + p * 8;
        cp16(sB_u32 + (unsigned)((0 * BK + r) * BN + bn) * 4u,
             B + (long)r * ldb + (col0 + bn));
    }
    cp_commit();
#pragma unroll
    for (int p = 0; p < 2; p++) {
        const int r = ar + p * 64;
        float4 v = *(const float4*)(A + (long)(row0 + r) * lda + ak);
        if (RELU_A) {
            v.x = fmaxf(v.x, 0.f); v.y = fmaxf(v.y, 0.f);
            v.z = fmaxf(v.z, 0.f); v.w = fmaxf(v.w, 0.f);
        }
        sA[0][ak + 0][r] = v.x; sA[0][ak + 1][r] = v.y;
        sA[0][ak + 2][r] = v.z; sA[0][ak + 3][r] = v.w;
    }
    cp_wait_all();
    __syncthreads();

    float acc[8][8];
#pragma unroll
    for (int i = 0; i < 8; i++)
#pragma unroll
        for (int j = 0; j < 8; j++) acc[i][j] = 0.f;

    const int ntiles = K / BK;
    int buf = 0;
    float4 aregs[2];

    for (int t = 0; t < ntiles; t++) {
        const int nb_  = buf ^ 1;
        const bool more = (t + 1 < ntiles);

        if (more) {
            const int k0 = (t + 1) * BK;
            // B tile t+1 -> other buffer (async, completes during compute)
#pragma unroll
            for (int p = 0; p < 2; p++) {
                const int r = bk + p * 8;
                cp16(sB_u32 + (unsigned)((nb_ * BK + r) * BN + bn) * 4u,
                     B + (long)(k0 + r) * ldb + (col0 + bn));
            }
            cp_commit();
            // A tile t+1 -> registers (scoreboard covers the compute below)
#pragma unroll
            for (int p = 0; p < 2; p++) {
                aregs[p] = *(const float4*)(A + (long)(row0 + ar + p * 64) * lda
                                              + (k0 + ak));
                if (RELU_A) {
                    aregs[p].x = fmaxf(aregs[p].x, 0.f);
                    aregs[p].y = fmaxf(aregs[p].y, 0.f);
                    aregs[p].z = fmaxf(aregs[p].z, 0.f);
                    aregs[p].w = fmaxf(aregs[p].w, 0.f);
                }
            }
        }

        // ---- compute current tile ----
#pragma unroll
        for (int kk = 0; kk < BK; kk++) {
            float ra[8], rb[8];
            *(float4*)(ra)     = *(const float4*)&sA[buf][kk][rm];
            *(float4*)(ra + 4) = *(const float4*)&sA[buf][kk][rm + 4];
            *(float4*)(rb)     = *(const float4*)&sB[buf][kk][rn];
            *(float4*)(rb + 4) = *(const float4*)&sB[buf][kk][rn + 4];
#pragma unroll
            for (int i = 0; i < 8; i++)
#pragma unroll
                for (int j = 0; j < 8; j++)
                    acc[i][j] = fmaf(ra[i], rb[j], acc[i][j]);
        }

        if (more) {
            // transpose-store A tile t+1 into other buffer
#pragma unroll
            for (int p = 0; p < 2; p++) {
                const int r = ar + p * 64;
                sA[nb_][ak + 0][r] = aregs[p].x;
                sA[nb_][ak + 1][r] = aregs[p].y;
                sA[nb_][ak + 2][r] = aregs[p].z;
                sA[nb_][ak + 3][r] = aregs[p].w;
            }
        }
        cp_wait_all();
        __syncthreads();
        buf = nb_;
    }

    // ---- epilogue: optional bias, vectorized store ----
#pragma unroll
    for (int i = 0; i < 8; i++) {
        float* crow = C + (long)(row0 + rm + i) * ldc + (col0 + rn);
#pragma unroll
        for (int j4 = 0; j4 < 8; j4 += 4) {
            float4 v;
            v.x = acc[i][j4 + 0]; v.y = acc[i][j4 + 1];
            v.z = acc[i][j4 + 2]; v.w = acc[i][j4 + 3];
            if (bias) {
                const float* bp = bias + col0 + rn + j4;
                v.x += bp[0]; v.y += bp[1]; v.z += bp[2]; v.w += bp[3];
            }
            *(float4*)(crow + j4) = v;
        }
    }
}

// ---------------------------------------------------------------------------
// Kernel 1: fused QKV projections. blockIdx.z in [0,9): op = z/3, head = z%3
// ---------------------------------------------------------------------------
__global__ __launch_bounds__(256, 2) void qkv_kernel(
    const float* __restrict__ t1, const float* __restrict__ t2,
    const float* __restrict__ Wq, const float* __restrict__ bq,
    const float* __restrict__ Wk, const float* __restrict__ bk,
    const float* __restrict__ Wv, const float* __restrict__ bv)
{
    const int z = blockIdx.z;
    const int op = z / 3;
    const int h  = z - op * 3;
    const long wOff = (long)h * HD * HD;
    const long cOff = (long)h * NB * SLQ * HD;

    const float* A; const float* W; const float* bias; float* Cb;
    if (op == 0)      { A = t1; W = Wq + wOff; bias = bq + h * HD; Cb = g_q + cOff; }
    else if (op == 1) { A = t2; W = Wk + wOff; bias = bk + h * HD; Cb = g_k + cOff; }
    else              { A = t2; W = Wv + wOff; bias = bv + h * HD; Cb = g_v + cOff; }

    gemm_nn<false>(A, W, Cb, bias, HD, HD, HD, HD);
}

// ---------------------------------------------------------------------------
// Kernel 1b: transpose K per (h,b): [n][d] -> [d][n]
// ---------------------------------------------------------------------------
__global__ __launch_bounds__(256) void transpose_k_kernel()
{
    __shared__ float t[32][33];
    const long z = blockIdx.z;
    const float* src = g_k  + z * (long)SLK * HD;   // [n][d]
    float*       dst = g_kT + z * (long)HD * SLK;   // [d][n]
    const int n0 = blockIdx.x * 32;
    const int d0 = blockIdx.y * 32;
    const int lx = threadIdx.x;        // 0..31
    const int ly = threadIdx.y;        // 0..7
#pragma unroll
    for (int i = ly; i < 32; i += 8)
        t[i][lx] = src[(long)(n0 + i) * HD + (d0 + lx)];
    __syncthreads();
#pragma unroll
    for (int i = ly; i < 32; i += 8)
        dst[(long)(d0 + i) * SLK + (n0 + lx)] = t[lx][i];
}

// ---------------------------------------------------------------------------
// Kernel 2: scores = q @ kT per (h,b). blockIdx.z = h*8 + b  (NN now)
// ---------------------------------------------------------------------------
__global__ __launch_bounds__(256, 2) void scores_kernel()
{
    const long z = blockIdx.z;
    gemm_nn<false>(g_q + z * SLQ * HD, g_kT + z * (long)HD * SLK,
                   g_s + z * SLQ * SLK, nullptr,
                   HD, HD, SLK, SLK);
}

// ---------------------------------------------------------------------------
// Kernel 3: row softmax over LK, in place. One 256-thread block per row.
// ---------------------------------------------------------------------------
__global__ void softmax_kernel()
{
    float* p = g_s + (long)blockIdx.x * SLK;
    const int tid = threadIdx.x;
    float4 v = reinterpret_cast<float4*>(p)[tid];

    __shared__ float redm[8];
    __shared__ float reds[8];

    float m = fmaxf(fmaxf(v.x, v.y), fmaxf(v.z, v.w));
#pragma unroll
    for (int o = 16; o > 0; o >>= 1) m = fmaxf(m, __shfl_xor_sync(0xffffffffu, m, o));
    if ((tid & 31) == 0) redm[tid >> 5] = m;
    __syncthreads();
    if (tid < 32) {
        float t = (tid < 8) ? redm[tid] : -INFINITY;
#pragma unroll
        for (int o = 4; o > 0; o >>= 1) t = fmaxf(t, __shfl_xor_sync(0xffffffffu, t, o));
        if (tid == 0) redm[0] = t;
    }
    __syncthreads();
    m = redm[0];

    v.x = __expf(v.x - m); v.y = __expf(v.y - m);
    v.z = __expf(v.z - m); v.w = __expf(v.w - m);
    float s = v.x + v.y + v.z + v.w;
#pragma unroll
    for (int o = 16; o > 0; o >>= 1) s += __shfl_xor_sync(0xffffffffu, s, o);
    if ((tid & 31) == 0) reds[tid >> 5] = s;
    __syncthreads();
    if (tid < 32) {
        float t = (tid < 8) ? reds[tid] : 0.f;
#pragma unroll
        for (int o = 4; o > 0; o >>= 1) t += __shfl_xor_sync(0xffffffffu, t, o);
        if (tid == 0) reds[0] = t;
    }
    __syncthreads();
    const float inv = 1.f / reds[0];

    v.x *= inv; v.y *= inv; v.z *= inv; v.w *= inv;
    reinterpret_cast<float4*>(p)[tid] = v;
}

// ---------------------------------------------------------------------------
// Kernel 4: ctx = P @ v per (h,b), scattered into multi[b][m][h*768 + e]
// ---------------------------------------------------------------------------
__global__ __launch_bounds__(256, 2) void ctx_kernel()
{
    const int z = blockIdx.z;
    const int h = z >> 3;
    const int b = z & 7;
    gemm_nn<false>(g_s + (long)z * SLQ * SLK,
                   g_v + (long)z * SLK * HD,
                   g_multi + (long)b * SLQ * (NH * HD) + (long)h * HD,
                   nullptr,
                   SLK, SLK, HD, NH * HD);
}

// ---------------------------------------------------------------------------
// Kernel 5: out = relu(multi) @ Wp + bp
// ---------------------------------------------------------------------------
__global__ __launch_bounds__(256, 2) void proj_kernel(
    const float* __restrict__ Wp, const float* __restrict__ bp,
    float* __restrict__ out)
{
    gemm_nn<true>(g_multi, Wp, out, bp, NH * HD, NH * HD, HD, HD);
}

// ---------------------------------------------------------------------------
// Launch
// ---------------------------------------------------------------------------
extern "C" void kernel_launch(void* const* d_in, const int* in_sizes, int n_in,
                              void* d_out, int out_size)
{
    const float* t1 = (const float*)d_in[0];   // [8,1024,768]
    const float* t2 = (const float*)d_in[1];   // [8,1024,768]
    const float* Wq = (const float*)d_in[2];   // [3,768,768]
    const float* bq = (const float*)d_in[3];   // [3,768]
    const float* Wk = (const float*)d_in[4];
    const float* bk = (const float*)d_in[5];
    const float* Wv = (const float*)d_in[6];
    const float* bv = (const float*)d_in[7];
    const float* Wp = (const float*)d_in[8];   // [2304,768]
    const float* bp = (const float*)d_in[9];   // [768]
    float* out = (float*)d_out;                // [8,1024,768]

    // QKV: M=8192, N=768 -> grid (6, 64, 9)
    qkv_kernel<<<dim3(6, 64, 9), 256>>>(t1, t2, Wq, bq, Wk, bk, Wv, bv);
    // K transpose: per (h,b) tile grid (1024/32, 768/32, 24)
    transpose_k_kernel<<<dim3(SLK / 32, HD / 32, NH * NB), dim3(32, 8)>>>();
    // scores: M=1024, N=1024 per (h,b) -> grid (8, 8, 24)
    scores_kernel<<<dim3(8, 8, 24), 256>>>();
    // softmax: one block per row
    softmax_kernel<<<NH * NB * SLQ, 256>>>();
    // ctx: M=1024, N=768 per (h,b) -> grid (6, 8, 24)
    ctx_kernel<<<dim3(6, 8, 24), 256>>>();
    // proj: M=8192, N=768 -> grid (6, 64, 1)
    proj_kernel<<<dim3(6, 64, 1), 256>>>(Wp, bp, out);
}